// round 1
// baseline (speedup 1.0000x reference)
#include <cuda_runtime.h>
#include <cstddef>

#define MAX_N 50000
#define MAX_E 800000
#define D 64

// Scratch (device globals — no allocation allowed)
__device__ __align__(16) float g_aS[MAX_N];
__device__ __align__(16) float g_aD[MAX_N];
__device__ __align__(16) float g_denom[MAX_N];
__device__ __align__(16) float g_zN[(size_t)MAX_N * D];   // sum ex * nfeats[src]
__device__ __align__(16) float g_zE[(size_t)MAX_N * D];   // sum ex * efeats
__device__ __align__(16) float g_Wbig[192 * 64];          // [Wo1; W1@Wo2; W2@Wo2]

// ---------------------------------------------------------------------------
// K0: fold weights.  Wbig rows 0-63 = W_out[0:64] (applies to nfeats),
// rows 64-127 = W_ne[0:64]@W_out[64:128] (applies to zN/denom),
// rows 128-191 = W_ne[64:128]@W_out[64:128] (applies to zE/denom).
// ---------------------------------------------------------------------------
__global__ void fold_kernel(const float* __restrict__ Wne,
                            const float* __restrict__ Wout) {
    int b = blockIdx.x;          // 0..191
    int j = threadIdx.x;         // 0..63
    if (b < 64) {
        g_Wbig[b * 64 + j] = Wout[b * 64 + j];
    } else {
        int i = b - 64;          // row of W_ne (0..127)
        float acc = 0.f;
#pragma unroll 16
        for (int k = 0; k < 64; ++k)
            acc += Wne[i * 64 + k] * Wout[(64 + k) * 64 + j];
        g_Wbig[b * 64 + j] = acc;
    }
}

// ---------------------------------------------------------------------------
// K1: per-node attention scalars a_src, a_dst + zero the accumulators.
// One warp per node. Lanes 0-15 dot with Wa[0:64], lanes 16-31 with Wa[64:128].
// ---------------------------------------------------------------------------
__global__ void node_pre_kernel(const float* __restrict__ nf,
                                const float* __restrict__ Wattn, int N) {
    int warp = (blockIdx.x * blockDim.x + threadIdx.x) >> 5;
    int lane = threadIdx.x & 31;
    if (warp >= N) return;

    const float4* x4p = (const float4*)(nf + (size_t)warp * D);
    float4 x = __ldg(x4p + (lane & 15));
    float4 w = __ldg(((const float4*)Wattn) + lane);   // lanes 16-31 hit Wa[64:128]
    float part = x.x * w.x + x.y * w.y + x.z * w.z + x.w * w.w;
    part += __shfl_xor_sync(0xffffffffu, part, 8);
    part += __shfl_xor_sync(0xffffffffu, part, 4);
    part += __shfl_xor_sync(0xffffffffu, part, 2);
    part += __shfl_xor_sync(0xffffffffu, part, 1);
    if (lane == 0)  g_aS[warp] = part;
    if (lane == 16) g_aD[warp] = part;

    // zero accumulators (float2 per lane = 64 floats per row)
    float2 z2 = make_float2(0.f, 0.f);
    ((float2*)(g_zN + (size_t)warp * D))[lane] = z2;
    ((float2*)(g_zE + (size_t)warp * D))[lane] = z2;
    if (lane == 1) g_denom[warp] = 0.f;
}

// ---------------------------------------------------------------------------
// K2: the single edge pass.  One warp per edge.
// Lanes 0-15 hold efeats row (float4 each), lanes 16-31 hold nfeats[src] row.
// e = lrelu(aS[src]+aD[dst]+ef.Wa_e+b); ex = exp(e) (max-subtraction elided,
// safe: |e| <~ 10).  Atomically accumulate denom, zE += ex*ef, zN += ex*h_src.
// ---------------------------------------------------------------------------
__global__ void edge_kernel(const float* __restrict__ ef,
                            const float* __restrict__ nf,
                            const float* __restrict__ Wattn,
                            const float* __restrict__ b_attn,
                            const int* __restrict__ src,
                            const int* __restrict__ dst, int E) {
    int e = (blockIdx.x * blockDim.x + threadIdx.x) >> 5;
    if (e >= E) return;
    int lane = threadIdx.x & 31;

    int s = __ldg(src + e);
    int d = __ldg(dst + e);

    float4 v;
    float part = 0.f;
    if (lane < 16) {
        v = __ldg((const float4*)ef + (size_t)e * 16 + lane);
        float4 w = __ldg((const float4*)(Wattn + 128) + lane);
        part = v.x * w.x + v.y * w.y + v.z * w.z + v.w * w.w;
    } else {
        v = __ldg((const float4*)nf + (size_t)s * 16 + (lane - 16));
    }
    part += __shfl_xor_sync(0xffffffffu, part, 8);
    part += __shfl_xor_sync(0xffffffffu, part, 4);
    part += __shfl_xor_sync(0xffffffffu, part, 2);
    part += __shfl_xor_sync(0xffffffffu, part, 1);
    float a_e = __shfl_sync(0xffffffffu, part, 0);

    float att = g_aS[s] + g_aD[d] + a_e + __ldg(b_attn);
    att = att > 0.f ? att : 0.01f * att;      // leaky_relu, slope 0.01
    float ex = __expf(att);

    if (lane == 0) atomicAdd(&g_denom[d], ex);

    float* base = (lane < 16) ? g_zE : g_zN;
    int col = (lane & 15) * 4;
    float4 c = make_float4(ex * v.x, ex * v.y, ex * v.z, ex * v.w);
    atomicAdd((float4*)(base + (size_t)d * D + col), c);  // sm_90+ vector RED
}

// ---------------------------------------------------------------------------
// K3: fused output GEMM.  out = relu(A @ Wbig),
// A[n] = [nfeats[n] (64) | r*zN[n] (64) | r*zE[n] (64)], r = denom>0 ? 1/denom : 0.
// Tile: 64 nodes x 64 cols, K in 3 chunks of 64 (one per source).
// 256 threads, 4x4 microtile each.
// ---------------------------------------------------------------------------
__global__ void out_gemm_kernel(const float* __restrict__ nf,
                                float* __restrict__ out, int N) {
    __shared__ float As[64 * 68];   // [k][node], stride 68 (16B-aligned rows)
    __shared__ float Bs[64 * 68];   // [k][col]
    __shared__ float rr[64];

    int tid = threadIdx.x;
    int n0 = blockIdx.x * 64;
    int tx = tid & 15;      // col group
    int ty = tid >> 4;      // row group
    int f  = tid & 15;      // float4 column for loads
    int r0 = tid >> 4;      // base row for loads

    if (tid < 64) {
        int n = n0 + tid;
        float dd = (n < N) ? g_denom[n] : 0.f;
        rr[tid] = dd > 0.f ? 1.f / dd : 0.f;
    }

    float acc[4][4];
#pragma unroll
    for (int i = 0; i < 4; ++i)
#pragma unroll
        for (int j = 0; j < 4; ++j) acc[i][j] = 0.f;

    for (int c = 0; c < 3; ++c) {
        const float* Sp = (c == 0) ? nf : (c == 1 ? g_zN : g_zE);
        __syncthreads();
#pragma unroll
        for (int l = 0; l < 4; ++l) {
            int row = r0 + 16 * l;
            int n = n0 + row;
            float4 v = make_float4(0.f, 0.f, 0.f, 0.f);
            if (n < N) v = __ldg((const float4*)(Sp + (size_t)n * 64) + f);
            if (c > 0) {
                float r = rr[row];
                v.x *= r; v.y *= r; v.z *= r; v.w *= r;
            }
            As[(4 * f + 0) * 68 + row] = v.x;
            As[(4 * f + 1) * 68 + row] = v.y;
            As[(4 * f + 2) * 68 + row] = v.z;
            As[(4 * f + 3) * 68 + row] = v.w;
            float4 b = __ldg((const float4*)(g_Wbig + (size_t)(c * 64 + row) * 64) + f);
            *(float4*)&Bs[row * 68 + 4 * f] = b;
        }
        __syncthreads();
#pragma unroll
        for (int k = 0; k < 64; ++k) {
            float4 a = *(const float4*)&As[k * 68 + ty * 4];
            float4 b = *(const float4*)&Bs[k * 68 + tx * 4];
            acc[0][0] += a.x * b.x; acc[0][1] += a.x * b.y; acc[0][2] += a.x * b.z; acc[0][3] += a.x * b.w;
            acc[1][0] += a.y * b.x; acc[1][1] += a.y * b.y; acc[1][2] += a.y * b.z; acc[1][3] += a.y * b.w;
            acc[2][0] += a.z * b.x; acc[2][1] += a.z * b.y; acc[2][2] += a.z * b.z; acc[2][3] += a.z * b.w;
            acc[3][0] += a.w * b.x; acc[3][1] += a.w * b.y; acc[3][2] += a.w * b.z; acc[3][3] += a.w * b.w;
        }
    }

#pragma unroll
    for (int i = 0; i < 4; ++i) {
        int n = n0 + ty * 4 + i;
        if (n < N) {
            float4 o;
            o.x = fmaxf(acc[i][0], 0.f);
            o.y = fmaxf(acc[i][1], 0.f);
            o.z = fmaxf(acc[i][2], 0.f);
            o.w = fmaxf(acc[i][3], 0.f);
            *(float4*)(out + (size_t)n * 64 + tx * 4) = o;
        }
    }
}

// ---------------------------------------------------------------------------
extern "C" void kernel_launch(void* const* d_in, const int* in_sizes, int n_in,
                              void* d_out, int out_size) {
    const float* nfeats = (const float*)d_in[0];
    const float* efeats = (const float*)d_in[1];
    const float* W_ne   = (const float*)d_in[2];
    const float* W_attn = (const float*)d_in[3];
    const float* b_attn = (const float*)d_in[4];
    const float* W_out  = (const float*)d_in[5];
    const int*   src    = (const int*)d_in[6];
    const int*   dst    = (const int*)d_in[7];
    float* out = (float*)d_out;

    int N = in_sizes[0] / D;
    int E = in_sizes[6];

    fold_kernel<<<192, 64>>>(W_ne, W_out);
    node_pre_kernel<<<(N * 32 + 255) / 256, 256>>>(nfeats, W_attn, N);
    edge_kernel<<<(E + 7) / 8, 256>>>(efeats, nfeats, W_attn, b_attn, src, dst, E);
    out_gemm_kernel<<<(N + 63) / 64, 256>>>(nfeats, out, N);
}